// round 13
// baseline (speedup 1.0000x reference)
#include <cuda_runtime.h>
#include <cstddef>

#define Nn   128
#define Lq   2048
#define NBat 2
#define Tc   32
#define NCH  64          // chunks per batch
#define GC   8           // chunks per group
#define NG   8           // groups per batch
#define NBLK 128         // co-resident blocks (1/SM)
#define NBAR 4

// Persistent device scratch (zero-initialized at module load)
__device__ float g_AdT[Nn * Nn];             // AdT[m][k] = Ad[k][m]
__device__ float g_Bd[Nn];
__device__ float g_P[Nn * Nn];               // P  = Ad^32   (row-major)
__device__ float g_P8[Nn * Nn];              // P8 = Ad^256  (row-major)
__device__ float g_lfin[NBat * NCH * Nn];    // chunk-local end states
__device__ float g_U[NBat * NG * Nn];        // group-local combines
__device__ float g_S[NBat * NG * Nn];        // group entering states
__device__ float g_c[NBat * Lq * Nn];        // all states (2 MB)
__device__ unsigned int g_cnt[NBAR];
__device__ unsigned int g_gen[NBAR];

// Self-resetting grid barrier (generation-tagged, graph-replay safe). Proven.
__device__ __forceinline__ void gbar(int idx, unsigned* s_tmp) {
    __syncthreads();
    if (threadIdx.x == 0) {
        unsigned my = *(volatile unsigned*)&g_gen[idx];
        __threadfence();
        unsigned t = atomicAdd(&g_cnt[idx], 1u);
        if (t == NBLK - 1) {
            g_cnt[idx] = 0;
            __threadfence();
            atomicAdd(&g_gen[idx], 1u);
        } else {
            while (*(volatile unsigned*)&g_gen[idx] == my) __nanosleep(64);
        }
        __threadfence();
        *s_tmp = my;
    }
    __syncthreads();
}

// ---- packed f32x2 helpers ----
__device__ __forceinline__ unsigned long long pack2(float lo, float hi) {
    unsigned long long r;
    asm("mov.b64 %0, {%1, %2};"
        : "=l"(r) : "r"(__float_as_uint(lo)), "r"(__float_as_uint(hi)));
    return r;
}
// 64-elem dot: a2[32] packed matrix pairs (regs) x 16B-aligned smem slice.
__device__ __forceinline__ float dot64p(const unsigned long long* __restrict__ a2,
                                        const float* __restrict__ st) {
    const ulonglong2* c2 = (const ulonglong2*)st;
    unsigned long long acc0 = 0ull, acc1 = 0ull;
    #pragma unroll
    for (int jj = 0; jj < 16; jj++) {
        ulonglong2 cv = c2[jj];
        asm("fma.rn.f32x2 %0, %1, %2, %0;" : "+l"(acc0) : "l"(a2[2 * jj    ]), "l"(cv.x));
        asm("fma.rn.f32x2 %0, %1, %2, %0;" : "+l"(acc1) : "l"(a2[2 * jj + 1]), "l"(cv.y));
    }
    unsigned lo0, hi0, lo1, hi1;
    asm("mov.b64 {%0, %1}, %2;" : "=r"(lo0), "=r"(hi0) : "l"(acc0));
    asm("mov.b64 {%0, %1}, %2;" : "=r"(lo1), "=r"(hi1) : "l"(acc1));
    return (__uint_as_float(lo0) + __uint_as_float(hi0))
         + (__uint_as_float(lo1) + __uint_as_float(hi1));
}

// ---------------------------------------------------------------------------
// Fused prelude. 128 blocks x 256 threads, 66048 B dyn smem, 1 block/SM.
// Thread layout for all scans: warp w owns k in [w*16,(w+1)*16); lane pair
// (2j, 2j+1) splits the 128-dot into m-halves; shfl_xor(1) combines.
// ONE __syncthreads per scan step (double-buffered state).
// ---------------------------------------------------------------------------
__global__ void __launch_bounds__(256, 1)
k_fused(const float* __restrict__ A, const float* __restrict__ Bv,
        const float* __restrict__ f, float* __restrict__ out) {
    extern __shared__ float sh[];            // padded 128x129 staging (stage A)
    __shared__ __align__(16) float cb[2][Nn];   // double-buffered scan state
    __shared__ __align__(16) float lsh[GC][Nn]; // prefetched l/U vectors
    __shared__ float fsh[Tc];
    __shared__ unsigned s_tmp;

    const int bid = blockIdx.x, tid = threadIdx.x;
    const int wid = tid >> 5, lane = tid & 31;
    const int k  = (wid << 4) | (lane >> 1);     // 0..127
    const int mh = lane & 1;                     // m-half
    const int m0 = mh << 6;
    const int b = bid >> 6, g = bid & 63;
    const int jg = g >> 3, ic = g & 7;           // group, index in group

    // ===== Stage A: warp-synchronous forward substitution (proven) =====
    for (int idx = tid; idx < Nn * Nn; idx += 256)
        sh[(idx >> 7) * 129 + (idx & 127)] = A[idx];
    __syncthreads();

    if (wid == 0 || (wid == 1 && bid == 0)) {
        const int c = (wid == 1) ? Nn : bid;
        float rr[4], rpiv[4], acc[4] = {0.f, 0.f, 0.f, 0.f}, sol[4];
        #pragma unroll
        for (int s = 0; s < 4; s++) {
            const int row = s * 32 + lane;
            rr[s]   = (c < Nn) ? ((row == c ? 1.f : 0.f) + 0.5f * sh[row * 129 + c])
                               : Bv[row];
            rpiv[s] = 1.f / (1.f - 0.5f * sh[row * 129 + row]);
        }
        #pragma unroll 4
        for (int j = 0; j < Nn; j++) {
            const int s = j >> 5, src = j & 31;
            float cand = (rr[s] - acc[s]) * rpiv[s];
            float xj = __shfl_sync(0xffffffffu, cand, src);
            if (lane == src) sol[s] = xj;
            #pragma unroll
            for (int s2 = 0; s2 < 4; s2++) {
                const int row = s2 * 32 + lane;
                if (row > j)
                    acc[s2] = fmaf(-0.5f * sh[row * 129 + j], xj, acc[s2]);
            }
        }
        #pragma unroll
        for (int s = 0; s < 4; s++) {
            const int row = s * 32 + lane;
            if (c < Nn) g_AdT[c * Nn + row] = sol[s];
            else        g_Bd[row]           = sol[s];
        }
    }
    gbar(0, &s_tmp);

    // ===== Stage B: phase 1 — per-chunk zero-init local scan =====
    // (Ad c)[k] = sum_m AdT[m][k] c[m]; this thread covers m in [m0,m0+64).
    {
        unsigned long long a2[32];
        #pragma unroll
        for (int j = 0; j < 32; j++)
            a2[j] = pack2(g_AdT[(m0 + 2 * j) * Nn + k],
                          g_AdT[(m0 + 2 * j + 1) * Nn + k]);
        const float bd = g_Bd[k];
        if (tid < Tc) fsh[tid] = f[b * Lq + g * Tc + tid];
        if (tid < Nn) cb[0][tid] = 0.f;
        __syncthreads();
        int p = 0;
        for (int d = 0; d < Tc; d++) {
            float x = dot64p(a2, cb[p] + m0);
            x += __shfl_xor_sync(0xffffffffu, x, 1);
            if (mh == 0) cb[p ^ 1][k] = fmaf(bd, fsh[d], x);
            __syncthreads();
            p ^= 1;
        }
        if (mh == 0) g_lfin[(b * NCH + g) * Nn + k] = cb[p][k];
    }

    // ===== Stage C: row bid of P=Ad^32 via v^T <- v^T Ad, v0 = e_bid =====
    // (v^T Ad)[k] = sum_m v[m] Ad[m][k] = sum_m AdT[k][m]... row k of AdT.
    {
        unsigned long long w2[32];
        #pragma unroll
        for (int j = 0; j < 32; j++)
            w2[j] = pack2(g_AdT[k * Nn + m0 + 2 * j],
                          g_AdT[k * Nn + m0 + 2 * j + 1]);
        __syncthreads();
        if (tid < Nn) cb[0][tid] = (tid == bid) ? 1.f : 0.f;
        __syncthreads();
        int p = 0;
        for (int d = 0; d < 32; d++) {
            float x = dot64p(w2, cb[p] + m0);
            x += __shfl_xor_sync(0xffffffffu, x, 1);
            if (mh == 0) cb[p ^ 1][k] = x;
            __syncthreads();
            p ^= 1;
        }
        if (mh == 0) g_P[bid * Nn + k] = cb[p][k];   // P[bid][k]
    }
    gbar(1, &s_tmp);

    // P row k in regs — used by D1 (group combine) and D3 (catch-up).
    unsigned long long pd2[32];
    #pragma unroll
    for (int j = 0; j < 32; j++)
        pd2[j] = pack2(g_P[k * Nn + m0 + 2 * j], g_P[k * Nn + m0 + 2 * j + 1]);

    // ===== Stage C2: row bid of P8=P^8 via 7 steps v^T <- v^T P =====
    // (v^T P)[k] = sum_m v[m] P[m][k]  -> column k of P.
    {
        unsigned long long c2p[32];
        #pragma unroll
        for (int j = 0; j < 32; j++)
            c2p[j] = pack2(g_P[(m0 + 2 * j) * Nn + k],
                           g_P[(m0 + 2 * j + 1) * Nn + k]);
        if (mh == 0) cb[0][k] = g_P[bid * Nn + k];   // v0 = row bid of P
        __syncthreads();
        int p = 0;
        for (int d = 0; d < 7; d++) {
            float x = dot64p(c2p, cb[p] + m0);
            x += __shfl_xor_sync(0xffffffffu, x, 1);
            if (mh == 0) cb[p ^ 1][k] = x;
            __syncthreads();
            p ^= 1;
        }
        if (mh == 0) g_P8[bid * Nn + k] = cb[p][k];
    }

    // ===== Stage D1: group-local combine, 16 blocks (one per group) =====
    // U_j = sum_{i=0..7} P^{7-i} l_{8j+i}  via u <- P u + l_i, u0 = 0.
    if (ic == 0) {
        for (int idx = tid; idx < GC * Nn; idx += 256)
            lsh[idx >> 7][idx & 127] = g_lfin[(b * NCH + jg * GC) * Nn + idx];
        if (tid < Nn) cb[0][tid] = 0.f;
        __syncthreads();
        int p = 0;
        for (int i = 0; i < GC; i++) {
            float x = dot64p(pd2, cb[p] + m0);
            x += __shfl_xor_sync(0xffffffffu, x, 1);
            if (mh == 0) cb[p ^ 1][k] = x + lsh[i][k];
            __syncthreads();
            p ^= 1;
        }
        if (mh == 0) g_U[(b * NG + jg) * Nn + k] = cb[p][k];
    }
    gbar(2, &s_tmp);

    // ===== Stage D2: scan group boundaries, 2 blocks (one per batch) =====
    // S_0 = 0; S_{j+1} = P8 S_j + U_j.  Stores S_j (group entering states).
    if (bid < NBat) {
        unsigned long long p8[32];
        #pragma unroll
        for (int j = 0; j < 32; j++)
            p8[j] = pack2(g_P8[k * Nn + m0 + 2 * j],
                          g_P8[k * Nn + m0 + 2 * j + 1]);
        for (int idx = tid; idx < NG * Nn; idx += 256)
            lsh[idx >> 7][idx & 127] = g_U[(bid * NG) * Nn + idx];
        if (tid < Nn) cb[0][tid] = 0.f;
        __syncthreads();
        int p = 0;
        for (int j = 0; j < NG; j++) {
            if (mh == 0) g_S[(bid * NG + j) * Nn + k] = cb[p][k];
            float x = dot64p(p8, cb[p] + m0);
            x += __shfl_xor_sync(0xffffffffu, x, 1);
            if (mh == 0) cb[p ^ 1][k] = x + lsh[j][k];
            __syncthreads();
            p ^= 1;
        }
    }
    gbar(3, &s_tmp);

    // ===== Stage D3: per-chunk catch-up (<=7 steps, all blocks parallel) =====
    // s_g = scan from S_jg over l_{8jg .. 8jg+ic-1}.
    {
        for (int idx = tid; idx < ic * Nn; idx += 256)
            lsh[idx >> 7][idx & 127] = g_lfin[(b * NCH + jg * GC) * Nn + idx];
        if (mh == 0) cb[0][k] = g_S[(b * NG + jg) * Nn + k];
        __syncthreads();
        int p = 0;
        for (int t = 0; t < ic; t++) {
            float x = dot64p(pd2, cb[p] + m0);
            x += __shfl_xor_sync(0xffffffffu, x, 1);
            if (mh == 0) cb[p ^ 1][k] = x + lsh[t][k];
            __syncthreads();
            p ^= 1;
        }

        // ===== Stage E: rescan chunk from s_g (in cb[p]); write states =====
        unsigned long long a2[32];
        #pragma unroll
        for (int j = 0; j < 32; j++)
            a2[j] = pack2(g_AdT[(m0 + 2 * j) * Nn + k],
                          g_AdT[(m0 + 2 * j + 1) * Nn + k]);
        const float bd = g_Bd[k];
        const size_t base = (size_t)(b * Lq + g * Tc) * Nn;
        for (int d = 0; d < Tc; d++) {
            float x = dot64p(a2, cb[p] + m0);
            x += __shfl_xor_sync(0xffffffffu, x, 1);
            if (mh == 0) {
                float cn = fmaf(bd, fsh[d], x);
                cb[p ^ 1][k] = cn;
                g_c[base + (size_t)d * Nn + k] = cn;
            }
            __syncthreads();
            p ^= 1;
        }
        if (mh == 0 && g == NCH - 1) out[b * Nn + k] = cb[p][k];   // c_fin
    }
}

// ---------------------------------------------------------------------------
// Broadcast: y[b,t,n,k] = C[n]*c[b,t,k] + D*f[b,t].  4096 blocks, one (b,t).
// Proven 40 us store engine — unchanged.
// ---------------------------------------------------------------------------
__global__ void k_bcast(const float* __restrict__ C, const float* __restrict__ Dv,
                        const float* __restrict__ f, float* __restrict__ out) {
    const int bt = blockIdx.x;
    const int tid = threadIdx.x, wid = tid >> 5, lane = tid & 31;
    __shared__ __align__(16) float csh[Nn];
    __shared__ float Csh[Nn];
    if (tid < Nn) {
        csh[tid] = g_c[(size_t)bt * Nn + tid];
        Csh[tid] = C[tid];
    }
    const float Df = Dv[0] * f[bt];
    __syncthreads();

    const float4 cv = ((const float4*)csh)[lane];
    float4* dst = (float4*)(out + 256 + ((size_t)bt << 14));
    #pragma unroll
    for (int it = 0; it < 16; it++) {
        const int n = it * 8 + wid;          // warp writes one full 512B row
        const float Cn = Csh[n];
        float4 v;
        v.x = fmaf(Cn, cv.x, Df);
        v.y = fmaf(Cn, cv.y, Df);
        v.z = fmaf(Cn, cv.z, Df);
        v.w = fmaf(Cn, cv.w, Df);
        dst[n * 32 + lane] = v;
    }
}

extern "C" void kernel_launch(void* const* d_in, const int* in_sizes, int n_in,
                              void* d_out, int out_size) {
    const float* f  = (const float*)d_in[0];
    const float* A  = (const float*)d_in[1];
    const float* Bv = (const float*)d_in[2];
    const float* C  = (const float*)d_in[3];
    const float* Dv = (const float*)d_in[4];
    float* out = (float*)d_out;

    const int smem = Nn * 129 * (int)sizeof(float);   // 66048 B
    cudaFuncSetAttribute(k_fused, cudaFuncAttributeMaxDynamicSharedMemorySize, smem);
    k_fused<<<NBLK, 256, smem>>>(A, Bv, f, out);
    k_bcast<<<NBat * Lq, 256>>>(C, Dv, f, out);
}

// round 14
// speedup vs baseline: 1.0165x; 1.0165x over previous
#include <cuda_runtime.h>
#include <cstddef>

#define Nn   128
#define Lq   2048
#define NBat 2
#define Tc   32
#define NCH  64          // chunks per batch
#define NBLK 128         // co-resident blocks (1/SM)
#define NBAR 3

// Persistent device scratch (zero-initialized at module load)
__device__ float g_AdT[Nn * Nn];             // AdT[m][k] = Ad[k][m]
__device__ float g_Bd[Nn];
__device__ float g_P[Nn * Nn];               // g_P[r][c] = (Ad^32)[r][c]
__device__ float g_lfin[NBat * NCH * Nn];
__device__ float g_s[NBat * NCH * Nn];
__device__ float g_c[NBat * Lq * Nn];        // all states (2 MB)
__device__ unsigned int g_cnt[NBAR];
__device__ unsigned int g_gen[NBAR];

// Self-resetting grid barrier — BUSY-WAIT version (no __nanosleep).
// Wakeup latency = one L2 poll (~250 cyc) instead of a sleep quantum.
__device__ __forceinline__ void gbar(int idx, unsigned* s_tmp) {
    __syncthreads();
    if (threadIdx.x == 0) {
        unsigned my = *(volatile unsigned*)&g_gen[idx];
        __threadfence();
        unsigned t = atomicAdd(&g_cnt[idx], 1u);
        if (t == NBLK - 1) {
            g_cnt[idx] = 0;
            __threadfence();
            atomicAdd(&g_gen[idx], 1u);
        } else {
            while (*(volatile unsigned*)&g_gen[idx] == my) { }
        }
        __threadfence();
        *s_tmp = my;
    }
    __syncthreads();
}

// ---- packed f32x2 helpers (ptxas never emits FFMA2 from C++) ----
__device__ __forceinline__ unsigned long long pack2(float lo, float hi) {
    unsigned long long r;
    asm("mov.b64 %0, {%1, %2};"
        : "=l"(r) : "r"(__float_as_uint(lo)), "r"(__float_as_uint(hi)));
    return r;
}
__device__ __forceinline__ float dot64p(const unsigned long long* __restrict__ a2,
                                        const float* __restrict__ st) {
    const ulonglong2* c2 = (const ulonglong2*)st;
    unsigned long long acc0 = 0ull, acc1 = 0ull;
    #pragma unroll
    for (int jj = 0; jj < 16; jj++) {
        ulonglong2 cv = c2[jj];
        asm("fma.rn.f32x2 %0, %1, %2, %0;" : "+l"(acc0) : "l"(a2[2 * jj    ]), "l"(cv.x));
        asm("fma.rn.f32x2 %0, %1, %2, %0;" : "+l"(acc1) : "l"(a2[2 * jj + 1]), "l"(cv.y));
    }
    unsigned lo0, hi0, lo1, hi1;
    asm("mov.b64 {%0, %1}, %2;" : "=r"(lo0), "=r"(hi0) : "l"(acc0));
    asm("mov.b64 {%0, %1}, %2;" : "=r"(lo1), "=r"(hi1) : "l"(acc1));
    return (__uint_as_float(lo0) + __uint_as_float(hi0))
         + (__uint_as_float(lo1) + __uint_as_float(hi1));
}

// ---------------------------------------------------------------------------
// Fused prelude (R12 structure — best passing config).
// 128 blocks x 256 threads, 66048 B dyn smem, 1 block/SM.
// ---------------------------------------------------------------------------
__global__ void __launch_bounds__(256, 1)
k_fused(const float* __restrict__ A, const float* __restrict__ Bv,
        const float* __restrict__ f, float* __restrict__ out) {
    extern __shared__ float sh[];            // padded 128x129 staging
    __shared__ __align__(16) float csh[Nn];
    __shared__ float psh[Nn];
    __shared__ float fsh[Tc];
    __shared__ unsigned s_tmp;

    const int bid = blockIdx.x, tid = threadIdx.x;
    const int k = tid & 127, h = tid >> 7, m0 = h * 64;
    const int b = bid >> 6, g = bid & 63;
    const int wid = tid >> 5, lane = tid & 31;

    // ===== Stage A: warp-synchronous forward substitution (proven) =====
    for (int idx = tid; idx < Nn * Nn; idx += 256)
        sh[(idx >> 7) * 129 + (idx & 127)] = A[idx];
    __syncthreads();

    if (wid == 0 || (wid == 1 && bid == 0)) {
        const int c = (wid == 1) ? Nn : bid;
        float rr[4], rpiv[4], acc[4] = {0.f, 0.f, 0.f, 0.f}, sol[4];
        #pragma unroll
        for (int s = 0; s < 4; s++) {
            const int row = s * 32 + lane;
            rr[s]   = (c < Nn) ? ((row == c ? 1.f : 0.f) + 0.5f * sh[row * 129 + c])
                               : Bv[row];
            rpiv[s] = 1.f / (1.f - 0.5f * sh[row * 129 + row]);
        }
        #pragma unroll 4
        for (int j = 0; j < Nn; j++) {
            const int s = j >> 5, src = j & 31;
            float cand = (rr[s] - acc[s]) * rpiv[s];
            float xj = __shfl_sync(0xffffffffu, cand, src);
            if (lane == src) sol[s] = xj;
            #pragma unroll
            for (int s2 = 0; s2 < 4; s2++) {
                const int row = s2 * 32 + lane;
                if (row > j)
                    acc[s2] = fmaf(-0.5f * sh[row * 129 + j], xj, acc[s2]);
            }
        }
        #pragma unroll
        for (int s = 0; s < 4; s++) {
            const int row = s * 32 + lane;
            if (c < Nn) g_AdT[c * Nn + row] = sol[s];
            else        g_Bd[row]           = sol[s];
        }
    }
    gbar(0, &s_tmp);

    // ===== Stage B: phase 1 — per-chunk zero-init local scan (FFMA2) =====
    unsigned long long a2[32];
    #pragma unroll
    for (int j = 0; j < 32; j++)
        a2[j] = pack2(g_AdT[(m0 + 2 * j) * Nn + k], g_AdT[(m0 + 2 * j + 1) * Nn + k]);
    const float bd = g_Bd[k];
    if (tid < Tc) fsh[tid] = f[b * Lq + g * Tc + tid];
    if (h == 0) csh[k] = 0.f;
    __syncthreads();
    {
        float cn = 0.f;
        for (int d = 0; d < Tc; d++) {
            float acc = dot64p(a2, csh + m0);
            if (h == 0) acc = fmaf(bd, fsh[d], acc);
            if (h == 1) psh[k] = acc;
            __syncthreads();
            if (h == 0) { cn = acc + psh[k]; csh[k] = cn; }
            __syncthreads();
        }
        if (h == 0) g_lfin[(b * NCH + g) * Nn + k] = cn;
    }

    // ===== Stage C: row bid of Ad^32 via v <- Ad^T v, v0 = e_bid (FFMA2) =====
    {
        unsigned long long w2[32];
        #pragma unroll
        for (int j = 0; j < 32; j++)
            w2[j] = pack2(g_AdT[k * Nn + m0 + 2 * j], g_AdT[k * Nn + m0 + 2 * j + 1]);
        __syncthreads();
        if (h == 0) csh[k] = (k == bid) ? 1.f : 0.f;
        __syncthreads();
        for (int d = 0; d < 32; d++) {
            float acc = dot64p(w2, csh + m0);
            if (h == 1) psh[k] = acc;
            __syncthreads();
            if (h == 0) csh[k] = acc + psh[k];
            __syncthreads();
        }
        if (h == 0) g_P[bid * Nn + k] = csh[k];    // Ad^32[bid][k]
    }
    gbar(1, &s_tmp);

    // ===== Stage D: phase 2 on blocks 0,1: s_{g+1} = Ad^32 s_g + lfin_g =====
    if (bid < NBat) {
        unsigned long long p2[32];
        #pragma unroll
        for (int j = 0; j < 32; j++)
            p2[j] = pack2(g_P[k * Nn + m0 + 2 * j], g_P[k * Nn + m0 + 2 * j + 1]);
        if (h == 0) { csh[k] = 0.f; g_s[(bid * NCH) * Nn + k] = 0.f; }
        __syncthreads();
        for (int gg = 1; gg < NCH; gg++) {
            float acc = dot64p(p2, csh + m0);
            if (h == 1) psh[k] = acc;
            __syncthreads();
            if (h == 0) {
                float cn = acc + psh[k] + g_lfin[(bid * NCH + gg - 1) * Nn + k];
                csh[k] = cn;
                g_s[(bid * NCH + gg) * Nn + k] = cn;
            }
            __syncthreads();
        }
    }
    gbar(2, &s_tmp);

    // ===== Stage E: rescan chunk from true entering state; write states =====
    {
        if (tid < Tc) fsh[tid] = f[b * Lq + g * Tc + tid];
        if (h == 0) csh[k] = g_s[(b * NCH + g) * Nn + k];
        __syncthreads();
        float cn = 0.f;
        for (int d = 0; d < Tc; d++) {
            float acc = dot64p(a2, csh + m0);
            if (h == 0) acc = fmaf(bd, fsh[d], acc);
            if (h == 1) psh[k] = acc;
            __syncthreads();
            if (h == 0) {
                cn = acc + psh[k];
                csh[k] = cn;
                g_c[(size_t)(b * Lq + g * Tc + d) * Nn + k] = cn;
            }
            __syncthreads();
        }
        if (h == 0 && g == NCH - 1) out[b * Nn + k] = cn;   // c_fin
    }
}

// ---------------------------------------------------------------------------
// Broadcast: y[b,t,n,k] = C[n]*c[b,t,k] + D*f[b,t].  4096 blocks, one (b,t).
// Proven store engine — unchanged.
// ---------------------------------------------------------------------------
__global__ void k_bcast(const float* __restrict__ C, const float* __restrict__ Dv,
                        const float* __restrict__ f, float* __restrict__ out) {
    const int bt = blockIdx.x;
    const int tid = threadIdx.x, wid = tid >> 5, lane = tid & 31;
    __shared__ __align__(16) float csh[Nn];
    __shared__ float Csh[Nn];
    if (tid < Nn) {
        csh[tid] = g_c[(size_t)bt * Nn + tid];
        Csh[tid] = C[tid];
    }
    const float Df = Dv[0] * f[bt];
    __syncthreads();

    const float4 cv = ((const float4*)csh)[lane];
    float4* dst = (float4*)(out + 256 + ((size_t)bt << 14));
    #pragma unroll
    for (int it = 0; it < 16; it++) {
        const int n = it * 8 + wid;          // warp writes one full 512B row
        const float Cn = Csh[n];
        float4 v;
        v.x = fmaf(Cn, cv.x, Df);
        v.y = fmaf(Cn, cv.y, Df);
        v.z = fmaf(Cn, cv.z, Df);
        v.w = fmaf(Cn, cv.w, Df);
        dst[n * 32 + lane] = v;
    }
}

// ---------------------------------------------------------------------------
// Empty dummies: pad the per-iteration launch count to 5 so ncu's
// "-s 5 -c 1" (skip 5, capture 1) lands on k_fused (index 5 mod 5 == 0)
// instead of k_bcast. Diagnostic scaffolding, ~1-2 us each.
// ---------------------------------------------------------------------------
__global__ void k_nop1() {}
__global__ void k_nop2() {}
__global__ void k_nop3() {}

extern "C" void kernel_launch(void* const* d_in, const int* in_sizes, int n_in,
                              void* d_out, int out_size) {
    const float* f  = (const float*)d_in[0];
    const float* A  = (const float*)d_in[1];
    const float* Bv = (const float*)d_in[2];
    const float* C  = (const float*)d_in[3];
    const float* Dv = (const float*)d_in[4];
    float* out = (float*)d_out;

    const int smem = Nn * 129 * (int)sizeof(float);   // 66048 B
    cudaFuncSetAttribute(k_fused, cudaFuncAttributeMaxDynamicSharedMemorySize, smem);
    k_fused<<<NBLK, 256, smem>>>(A, Bv, f, out);
    k_bcast<<<NBat * Lq, 256>>>(C, Dv, f, out);
    k_nop1<<<1, 32>>>();
    k_nop2<<<1, 32>>>();
    k_nop3<<<1, 32>>>();
}